// round 1
// baseline (speedup 1.0000x reference)
#include <cuda_runtime.h>
#include <cstdint>

#define NNODES 100000
#define DIM 128
#define MAXEDGE 1700000

// ---------------- device scratch (static, no allocation) ----------------
__device__ float g_hA[NNODES * DIM];
__device__ float g_hB[NNODES * DIM];
__device__ float g_agg[NNODES * DIM];
__device__ int   g_cnt[NNODES];
__device__ int   g_tmp[NNODES];
__device__ int   g_rowptr[NNODES + 1];
__device__ int   g_cursor[NNODES];
__device__ int   g_col[MAXEDGE];
__device__ int   g_part[256];
__device__ int   g_partscan[256];

// ---------------- CSR build ----------------
__global__ void k_zero_cnt() {
    int i = blockIdx.x * blockDim.x + threadIdx.x;
    if (i < NNODES) g_cnt[i] = 0;
}

__global__ void k_hist(const int* __restrict__ dst, int E) {
    int e = blockIdx.x * blockDim.x + threadIdx.x;
    if (e < E) atomicAdd(&g_cnt[dst[e]], 1);
}

__global__ void k_scan1() {
    __shared__ int s[512];
    int t = threadIdx.x;
    int i = blockIdx.x * 512 + t;
    int v = (i < NNODES) ? g_cnt[i] : 0;
    s[t] = v;
    __syncthreads();
#pragma unroll
    for (int off = 1; off < 512; off <<= 1) {
        int x = (t >= off) ? s[t - off] : 0;
        __syncthreads();
        s[t] += x;
        __syncthreads();
    }
    if (i < NNODES) g_tmp[i] = s[t] - v;   // exclusive within block
    if (t == 511) g_part[blockIdx.x] = s[511];
}

__global__ void k_scan2(int nblocks) {
    __shared__ int s[256];
    int t = threadIdx.x;
    int v = (t < nblocks) ? g_part[t] : 0;
    s[t] = v;
    __syncthreads();
#pragma unroll
    for (int off = 1; off < 256; off <<= 1) {
        int x = (t >= off) ? s[t - off] : 0;
        __syncthreads();
        s[t] += x;
        __syncthreads();
    }
    g_partscan[t] = s[t] - v;              // exclusive block offsets
}

__global__ void k_scan3(int E) {
    int i = blockIdx.x * blockDim.x + threadIdx.x;
    if (i < NNODES) {
        int r = g_tmp[i] + g_partscan[i >> 9];
        g_rowptr[i] = r;
        g_cursor[i] = r;
    }
    if (i == 0) g_rowptr[NNODES] = E;
}

__global__ void k_scatter(const int* __restrict__ src, const int* __restrict__ dst, int E) {
    int e = blockIdx.x * blockDim.x + threadIdx.x;
    if (e < E) {
        int p = atomicAdd(&g_cursor[dst[e]], 1);
        g_col[p] = src[e];
    }
}

// ---------------- SpMM: agg[i,:] = sum_{j in adj(i)} h[j,:] ----------------
__global__ void __launch_bounds__(256) k_spmm(const float* __restrict__ h) {
    int gw = (blockIdx.x * blockDim.x + threadIdx.x) >> 5;
    if (gw >= NNODES) return;
    int lane = threadIdx.x & 31;
    int s = g_rowptr[gw];
    int e = g_rowptr[gw + 1];
    const float4* hv = (const float4*)h;
    float4 acc = make_float4(0.f, 0.f, 0.f, 0.f);
    int i = s;
    for (; i + 4 <= e; i += 4) {
        int n0 = g_col[i], n1 = g_col[i + 1], n2 = g_col[i + 2], n3 = g_col[i + 3];
        float4 a = __ldg(&hv[n0 * 32 + lane]);
        float4 b = __ldg(&hv[n1 * 32 + lane]);
        float4 c = __ldg(&hv[n2 * 32 + lane]);
        float4 d = __ldg(&hv[n3 * 32 + lane]);
        acc.x += (a.x + b.x) + (c.x + d.x);
        acc.y += (a.y + b.y) + (c.y + d.y);
        acc.z += (a.z + b.z) + (c.z + d.z);
        acc.w += (a.w + b.w) + (c.w + d.w);
    }
    for (; i < e; i++) {
        int n = g_col[i];
        float4 a = __ldg(&hv[n * 32 + lane]);
        acc.x += a.x; acc.y += a.y; acc.z += a.z; acc.w += a.w;
    }
    ((float4*)g_agg)[gw * 32 + lane] = acc;
}

// ---------------- fused GEMM + bias + (residual) + ReLU + LayerNorm ----------------
// out = epilogue( agg @ Wrel + b + hin @ Wroot )
// mode 0: ReLU+LN            (layer 0)
// mode 1: +residual, ReLU+LN (middle layers)
// mode 2: plain              (output layer)
// block: 256 threads = 8 warps, 64 rows/block; warp = 8 rows, lane = 4 cols.
#define GEMM_SMEM_BYTES ((256 * 128 + 64 * 32) * 4)

__global__ void __launch_bounds__(256, 1) k_gemm(
    const float* __restrict__ hin,
    const float* __restrict__ Wrel, const float* __restrict__ Wroot,
    const float* __restrict__ bias,
    const float* __restrict__ gamma, const float* __restrict__ beta,
    float* __restrict__ hout, int mode)
{
    extern __shared__ float smem[];
    float* sW = smem;                 // [256][128]: rows 0..127 = Wrel, 128..255 = Wroot
    float* sA = smem + 256 * 128;     // [64][32] staged activation chunk

    int t = threadIdx.x;
    int warp = t >> 5;
    int lane = t & 31;

    // stage concatenated weights
    {
        const float4* wr = (const float4*)Wrel;
        const float4* wt = (const float4*)Wroot;
        float4* sW4 = (float4*)sW;
        for (int i = t; i < 128 * 32; i += 256) sW4[i] = wr[i];
        for (int i = t; i < 128 * 32; i += 256) sW4[128 * 32 + i] = wt[i];
    }

    int rowBase = blockIdx.x * 64;
    unsigned long long acc[8][2];
#pragma unroll
    for (int r = 0; r < 8; r++) { acc[r][0] = 0ull; acc[r][1] = 0ull; }

    const float* aggp = g_agg;

    for (int kb = 0; kb < 8; kb++) {
        const float* srcp = (kb < 4) ? aggp : hin;
        int kofs = (kb & 3) * 32;
        __syncthreads();
        // stage sA[64][32]
        for (int i = t; i < 512; i += 256) {
            int r = i >> 3;
            int kk4 = (i & 7) * 4;
            int grow = rowBase + r;
            float4 v = make_float4(0.f, 0.f, 0.f, 0.f);
            if (grow < NNODES) v = *(const float4*)&srcp[grow * 128 + kofs + kk4];
            *(float4*)&sA[r * 32 + kk4] = v;
        }
        __syncthreads();

#pragma unroll 8
        for (int kk = 0; kk < 32; kk++) {
            int k = kb * 32 + kk;
            float4 w = *(float4*)&sW[k * 128 + lane * 4];
            unsigned long long w01, w23;
            asm("mov.b64 %0, {%1,%2};" : "=l"(w01) : "f"(w.x), "f"(w.y));
            asm("mov.b64 %0, {%1,%2};" : "=l"(w23) : "f"(w.z), "f"(w.w));
#pragma unroll
            for (int r = 0; r < 8; r++) {
                float a = sA[(warp * 8 + r) * 32 + kk];
                unsigned long long aa;
                asm("mov.b64 %0, {%1,%1};" : "=l"(aa) : "f"(a));
                asm("fma.rn.f32x2 %0, %1, %2, %0;" : "+l"(acc[r][0]) : "l"(aa), "l"(w01));
                asm("fma.rn.f32x2 %0, %1, %2, %0;" : "+l"(acc[r][1]) : "l"(aa), "l"(w23));
            }
        }
    }

    // ---- epilogue ----
    float4 bv  = *(const float4*)&bias[lane * 4];
    float4 gv  = *(const float4*)&gamma[lane * 4];
    float4 btv = *(const float4*)&beta[lane * 4];

#pragma unroll
    for (int r = 0; r < 8; r++) {
        int row = rowBase + warp * 8 + r;
        if (row >= NNODES) continue;   // uniform across warp
        float v0, v1, v2, v3;
        asm("mov.b64 {%0,%1}, %2;" : "=f"(v0), "=f"(v1) : "l"(acc[r][0]));
        asm("mov.b64 {%0,%1}, %2;" : "=f"(v2), "=f"(v3) : "l"(acc[r][1]));
        v0 += bv.x; v1 += bv.y; v2 += bv.z; v3 += bv.w;

        if (mode == 2) {
            float4 o = make_float4(v0, v1, v2, v3);
            *(float4*)&hout[row * 128 + lane * 4] = o;
            continue;
        }
        if (mode == 1) {
            float4 hres = *(const float4*)&hin[row * 128 + lane * 4];
            v0 += hres.x; v1 += hres.y; v2 += hres.z; v3 += hres.w;
        }
        v0 = fmaxf(v0, 0.f); v1 = fmaxf(v1, 0.f);
        v2 = fmaxf(v2, 0.f); v3 = fmaxf(v3, 0.f);

        float s1 = (v0 + v1) + (v2 + v3);
        float s2 = (v0 * v0 + v1 * v1) + (v2 * v2 + v3 * v3);
#pragma unroll
        for (int off = 16; off > 0; off >>= 1) {
            s1 += __shfl_xor_sync(0xffffffffu, s1, off);
            s2 += __shfl_xor_sync(0xffffffffu, s2, off);
        }
        float mean = s1 * (1.0f / 128.0f);
        float var  = s2 * (1.0f / 128.0f) - mean * mean;
        float rs   = rsqrtf(var + 1e-5f);

        float4 o;
        o.x = (v0 - mean) * rs * gv.x + btv.x;
        o.y = (v1 - mean) * rs * gv.y + btv.y;
        o.z = (v2 - mean) * rs * gv.z + btv.z;
        o.w = (v3 - mean) * rs * gv.w + btv.w;
        *(float4*)&hout[row * 128 + lane * 4] = o;
    }
}

// ---------------- host ----------------
extern "C" void kernel_launch(void* const* d_in, const int* in_sizes, int n_in,
                              void* d_out, int out_size)
{
    const float* in_feat = (const float*)d_in[0];
    const int*   eidx    = (const int*)d_in[1];
    const float* W_rel   = (const float*)d_in[2];
    const float* b_rel   = (const float*)d_in[3];
    const float* W_root  = (const float*)d_in[4];
    const float* gamma   = (const float*)d_in[5];
    const float* beta    = (const float*)d_in[6];
    float* out = (float*)d_out;

    int E = in_sizes[1] / 2;
    const int* src = eidx;
    const int* dst = eidx + E;

    float *hA, *hB;
    cudaGetSymbolAddress((void**)&hA, g_hA);
    cudaGetSymbolAddress((void**)&hB, g_hB);

    cudaFuncSetAttribute(k_gemm, cudaFuncAttributeMaxDynamicSharedMemorySize, GEMM_SMEM_BYTES);

    int nb_nodes = (NNODES + 255) / 256;
    int nb_edges = (E + 255) / 256;
    int nb_scan  = (NNODES + 511) / 512;

    // CSR build (per launch — deterministic work)
    k_zero_cnt<<<nb_nodes, 256>>>();
    k_hist<<<nb_edges, 256>>>(dst, E);
    k_scan1<<<nb_scan, 512>>>();
    k_scan2<<<1, 256>>>(nb_scan);
    k_scan3<<<nb_nodes, 256>>>(E);
    k_scatter<<<nb_edges, 256>>>(src, dst, E);

    int spmm_blocks = (NNODES * 32 + 255) / 256;   // one warp per node
    int gemm_blocks = (NNODES + 63) / 64;

    // layer 0: conv(in_feat) -> ReLU -> LN -> hA
    k_spmm<<<spmm_blocks, 256>>>(in_feat);
    k_gemm<<<gemm_blocks, 256, GEMM_SMEM_BYTES>>>(in_feat, W_rel, W_root, b_rel,
                                                  gamma, beta, hA, 0);
    // layer 1: conv(hA)+hA -> ReLU -> LN -> hB
    k_spmm<<<spmm_blocks, 256>>>(hA);
    k_gemm<<<gemm_blocks, 256, GEMM_SMEM_BYTES>>>(hA, W_rel + 1 * 128 * 128, W_root + 1 * 128 * 128,
                                                  b_rel + 1 * 128, gamma, beta, hB, 1);
    // layer 2: conv(hB)+hB -> ReLU -> LN -> hA
    k_spmm<<<spmm_blocks, 256>>>(hB);
    k_gemm<<<gemm_blocks, 256, GEMM_SMEM_BYTES>>>(hB, W_rel + 2 * 128 * 128, W_root + 2 * 128 * 128,
                                                  b_rel + 2 * 128, gamma, beta, hA, 1);
    // layer 3: conv(hA) -> out (no epilogue)
    k_spmm<<<spmm_blocks, 256>>>(hA);
    k_gemm<<<gemm_blocks, 256, GEMM_SMEM_BYTES>>>(hA, W_rel + 3 * 128 * 128, W_root + 3 * 128 * 128,
                                                  b_rel + 3 * 128, gamma, beta, out, 2);
}

// round 2
// speedup vs baseline: 1.1297x; 1.1297x over previous
#include <cuda_runtime.h>
#include <cstdint>

#define NNODES 100000
#define DIM 128
#define MAXEDGE 1700000
#define PAD 132

typedef unsigned long long ull;

// ---------------- device scratch (static, no allocation) ----------------
__device__ float g_hA[NNODES * DIM];
__device__ float g_hB[NNODES * DIM];
__device__ float g_agg[NNODES * DIM];
__device__ int   g_cnt[NNODES];
__device__ int   g_tmp[NNODES];
__device__ int   g_rowptr[NNODES + 1];
__device__ int   g_cursor[NNODES];
__device__ int   g_col[MAXEDGE];
__device__ int   g_part[256];
__device__ int   g_partscan[256];

// ---------------- CSR build ----------------
__global__ void k_zero_cnt() {
    int i = blockIdx.x * blockDim.x + threadIdx.x;
    if (i < NNODES) g_cnt[i] = 0;
}

__global__ void k_hist(const int* __restrict__ dst, int E) {
    int e = blockIdx.x * blockDim.x + threadIdx.x;
    if (e < E) atomicAdd(&g_cnt[dst[e]], 1);
}

__global__ void k_scan1() {
    __shared__ int s[512];
    int t = threadIdx.x;
    int i = blockIdx.x * 512 + t;
    int v = (i < NNODES) ? g_cnt[i] : 0;
    s[t] = v;
    __syncthreads();
#pragma unroll
    for (int off = 1; off < 512; off <<= 1) {
        int x = (t >= off) ? s[t - off] : 0;
        __syncthreads();
        s[t] += x;
        __syncthreads();
    }
    if (i < NNODES) g_tmp[i] = s[t] - v;   // exclusive within block
    if (t == 511) g_part[blockIdx.x] = s[511];
}

__global__ void k_scan2(int nblocks) {
    __shared__ int s[256];
    int t = threadIdx.x;
    int v = (t < nblocks) ? g_part[t] : 0;
    s[t] = v;
    __syncthreads();
#pragma unroll
    for (int off = 1; off < 256; off <<= 1) {
        int x = (t >= off) ? s[t - off] : 0;
        __syncthreads();
        s[t] += x;
        __syncthreads();
    }
    g_partscan[t] = s[t] - v;              // exclusive block offsets
}

__global__ void k_scan3(int E) {
    int i = blockIdx.x * blockDim.x + threadIdx.x;
    if (i < NNODES) {
        int r = g_tmp[i] + g_partscan[i >> 9];
        g_rowptr[i] = r;
        g_cursor[i] = r;
    }
    if (i == 0) g_rowptr[NNODES] = E;
}

__global__ void k_scatter(const int* __restrict__ src, const int* __restrict__ dst, int E) {
    int e = blockIdx.x * blockDim.x + threadIdx.x;
    if (e < E) {
        int p = atomicAdd(&g_cursor[dst[e]], 1);
        g_col[p] = src[e];
    }
}

// ---------------- SpMM: agg[i,:] = sum_{j in adj(i)} h[j,:] ----------------
__global__ void __launch_bounds__(256) k_spmm(const float* __restrict__ h) {
    int gw = (blockIdx.x * blockDim.x + threadIdx.x) >> 5;
    if (gw >= NNODES) return;
    int lane = threadIdx.x & 31;
    int s = g_rowptr[gw];
    int e = g_rowptr[gw + 1];
    const float4* hv = (const float4*)h;
    float4 acc = make_float4(0.f, 0.f, 0.f, 0.f);
    int i = s;
    for (; i + 4 <= e; i += 4) {
        int n0 = g_col[i], n1 = g_col[i + 1], n2 = g_col[i + 2], n3 = g_col[i + 3];
        float4 a = __ldg(&hv[n0 * 32 + lane]);
        float4 b = __ldg(&hv[n1 * 32 + lane]);
        float4 c = __ldg(&hv[n2 * 32 + lane]);
        float4 d = __ldg(&hv[n3 * 32 + lane]);
        acc.x += (a.x + b.x) + (c.x + d.x);
        acc.y += (a.y + b.y) + (c.y + d.y);
        acc.z += (a.z + b.z) + (c.z + d.z);
        acc.w += (a.w + b.w) + (c.w + d.w);
    }
    for (; i < e; i++) {
        int n = g_col[i];
        float4 a = __ldg(&hv[n * 32 + lane]);
        acc.x += a.x; acc.y += a.y; acc.z += a.z; acc.w += a.w;
    }
    ((float4*)g_agg)[gw * 32 + lane] = acc;
}

// ---------------- fused GEMM + bias + (residual) + ReLU + LayerNorm ----------------
// out = epilogue( agg @ Wrel + b + hin @ Wroot )
// mode 0: ReLU+LN ; mode 1: +residual, ReLU+LN ; mode 2: plain
// block: 256 threads = 8 warps, 128 rows/block; warp = 16 rows (8 row-pairs),
// lane = 4 cols. Accumulators are f32x2 over row-pairs; A comes pre-packed
// from a transposed smem tile via ld.shared.v2.b64 (zero pack instructions).
#define GEMM_SMEM_BYTES ((256 * 128 + 32 * PAD) * 4)

__global__ void __launch_bounds__(256, 1) k_gemm(
    const float* __restrict__ hin,
    const float* __restrict__ Wrel, const float* __restrict__ Wroot,
    const float* __restrict__ bias,
    const float* __restrict__ gamma, const float* __restrict__ beta,
    float* __restrict__ hout, int mode)
{
    extern __shared__ float smem[];
    float* sW  = smem;                 // [256][128]: rows 0..127 = Wrel, 128..255 = Wroot
    float* sAT = smem + 256 * 128;     // [32][PAD] transposed activation chunk: sAT[k][row]

    int t = threadIdx.x;
    int warp = t >> 5;
    int lane = t & 31;

    // stage concatenated weights
    {
        const float4* wr = (const float4*)Wrel;
        const float4* wt = (const float4*)Wroot;
        float4* sW4 = (float4*)sW;
        for (int i = t; i < 128 * 32; i += 256) sW4[i] = wr[i];
        for (int i = t; i < 128 * 32; i += 256) sW4[128 * 32 + i] = wt[i];
    }

    int rowBase = blockIdx.x * 128;

    ull acc[8][4];
#pragma unroll
    for (int rp = 0; rp < 8; rp++)
#pragma unroll
        for (int c = 0; c < 4; c++) acc[rp][c] = 0ull;

    const float* aggp = g_agg;

    for (int kb = 0; kb < 8; kb++) {
        const float* srcp = (kb < 4) ? aggp : hin;
        int kofs = (kb & 3) * 32;
        __syncthreads();
        // stage transposed: sAT[k][row], 128 rows x 32 k
        for (int i = t; i < 1024; i += 256) {
            int r  = i >> 3;          // 0..127
            int kq = (i & 7) * 4;     // 0,4,..,28
            int grow = rowBase + r;
            float4 v = make_float4(0.f, 0.f, 0.f, 0.f);
            if (grow < NNODES) v = *(const float4*)&srcp[grow * 128 + kofs + kq];
            sAT[(kq + 0) * PAD + r] = v.x;
            sAT[(kq + 1) * PAD + r] = v.y;
            sAT[(kq + 2) * PAD + r] = v.z;
            sAT[(kq + 3) * PAD + r] = v.w;
        }
        __syncthreads();

#pragma unroll 8
        for (int kk = 0; kk < 32; kk++) {
            int k = kb * 32 + kk;
            float4 w = *(float4*)&sW[k * 128 + lane * 4];
            ull wd[4];
            asm("mov.b64 %0, {%1,%1};" : "=l"(wd[0]) : "f"(w.x));
            asm("mov.b64 %0, {%1,%1};" : "=l"(wd[1]) : "f"(w.y));
            asm("mov.b64 %0, {%1,%1};" : "=l"(wd[2]) : "f"(w.z));
            asm("mov.b64 %0, {%1,%1};" : "=l"(wd[3]) : "f"(w.w));

            const float* arow = &sAT[kk * PAD + warp * 16];
            ulonglong2 p0 = *(const ulonglong2*)(arow + 0);
            ulonglong2 p1 = *(const ulonglong2*)(arow + 4);
            ulonglong2 p2 = *(const ulonglong2*)(arow + 8);
            ulonglong2 p3 = *(const ulonglong2*)(arow + 12);
            ull ap[8] = {p0.x, p0.y, p1.x, p1.y, p2.x, p2.y, p3.x, p3.y};

#pragma unroll
            for (int rp = 0; rp < 8; rp++) {
#pragma unroll
                for (int c = 0; c < 4; c++) {
                    asm("fma.rn.f32x2 %0, %1, %2, %0;"
                        : "+l"(acc[rp][c]) : "l"(ap[rp]), "l"(wd[c]));
                }
            }
        }
    }

    // ---- epilogue ----
    float4 bv  = *(const float4*)&bias[lane * 4];
    float4 gv  = *(const float4*)&gamma[lane * 4];
    float4 btv = *(const float4*)&beta[lane * 4];

#pragma unroll
    for (int rp = 0; rp < 8; rp++) {
        float va[2][4];
#pragma unroll
        for (int c = 0; c < 4; c++) {
            asm("mov.b64 {%0,%1}, %2;" : "=f"(va[0][c]), "=f"(va[1][c]) : "l"(acc[rp][c]));
        }
#pragma unroll
        for (int j = 0; j < 2; j++) {
            int row = rowBase + warp * 16 + rp * 2 + j;
            if (row >= NNODES) continue;   // uniform across warp
            float v0 = va[j][0] + bv.x;
            float v1 = va[j][1] + bv.y;
            float v2 = va[j][2] + bv.z;
            float v3 = va[j][3] + bv.w;

            if (mode == 2) {
                float4 o = make_float4(v0, v1, v2, v3);
                *(float4*)&hout[row * 128 + lane * 4] = o;
                continue;
            }
            if (mode == 1) {
                float4 hres = *(const float4*)&hin[row * 128 + lane * 4];
                v0 += hres.x; v1 += hres.y; v2 += hres.z; v3 += hres.w;
            }
            v0 = fmaxf(v0, 0.f); v1 = fmaxf(v1, 0.f);
            v2 = fmaxf(v2, 0.f); v3 = fmaxf(v3, 0.f);

            float s1 = (v0 + v1) + (v2 + v3);
            float s2 = (v0 * v0 + v1 * v1) + (v2 * v2 + v3 * v3);
#pragma unroll
            for (int off = 16; off > 0; off >>= 1) {
                s1 += __shfl_xor_sync(0xffffffffu, s1, off);
                s2 += __shfl_xor_sync(0xffffffffu, s2, off);
            }
            float mean = s1 * (1.0f / 128.0f);
            float var  = s2 * (1.0f / 128.0f) - mean * mean;
            float rs   = rsqrtf(var + 1e-5f);

            float4 o;
            o.x = (v0 - mean) * rs * gv.x + btv.x;
            o.y = (v1 - mean) * rs * gv.y + btv.y;
            o.z = (v2 - mean) * rs * gv.z + btv.z;
            o.w = (v3 - mean) * rs * gv.w + btv.w;
            *(float4*)&hout[row * 128 + lane * 4] = o;
        }
    }
}

// ---------------- host ----------------
extern "C" void kernel_launch(void* const* d_in, const int* in_sizes, int n_in,
                              void* d_out, int out_size)
{
    const float* in_feat = (const float*)d_in[0];
    const int*   eidx    = (const int*)d_in[1];
    const float* W_rel   = (const float*)d_in[2];
    const float* b_rel   = (const float*)d_in[3];
    const float* W_root  = (const float*)d_in[4];
    const float* gamma   = (const float*)d_in[5];
    const float* beta    = (const float*)d_in[6];
    float* out = (float*)d_out;

    int E = in_sizes[1] / 2;
    const int* src = eidx;
    const int* dst = eidx + E;

    float *hA, *hB;
    cudaGetSymbolAddress((void**)&hA, g_hA);
    cudaGetSymbolAddress((void**)&hB, g_hB);

    cudaFuncSetAttribute(k_gemm, cudaFuncAttributeMaxDynamicSharedMemorySize, GEMM_SMEM_BYTES);

    int nb_nodes = (NNODES + 255) / 256;
    int nb_edges = (E + 255) / 256;
    int nb_scan  = (NNODES + 511) / 512;

    // CSR build (per launch — deterministic work)
    k_zero_cnt<<<nb_nodes, 256>>>();
    k_hist<<<nb_edges, 256>>>(dst, E);
    k_scan1<<<nb_scan, 512>>>();
    k_scan2<<<1, 256>>>(nb_scan);
    k_scan3<<<nb_nodes, 256>>>(E);
    k_scatter<<<nb_edges, 256>>>(src, dst, E);

    int spmm_blocks = (NNODES * 32 + 255) / 256;   // one warp per node
    int gemm_blocks = (NNODES + 127) / 128;

    // layer 0: conv(in_feat) -> ReLU -> LN -> hA
    k_spmm<<<spmm_blocks, 256>>>(in_feat);
    k_gemm<<<gemm_blocks, 256, GEMM_SMEM_BYTES>>>(in_feat, W_rel, W_root, b_rel,
                                                  gamma, beta, hA, 0);
    // layer 1: conv(hA)+hA -> ReLU -> LN -> hB
    k_spmm<<<spmm_blocks, 256>>>(hA);
    k_gemm<<<gemm_blocks, 256, GEMM_SMEM_BYTES>>>(hA, W_rel + 1 * 128 * 128, W_root + 1 * 128 * 128,
                                                  b_rel + 1 * 128, gamma, beta, hB, 1);
    // layer 2: conv(hB)+hB -> ReLU -> LN -> hA
    k_spmm<<<spmm_blocks, 256>>>(hB);
    k_gemm<<<gemm_blocks, 256, GEMM_SMEM_BYTES>>>(hB, W_rel + 2 * 128 * 128, W_root + 2 * 128 * 128,
                                                  b_rel + 2 * 128, gamma, beta, hA, 1);
    // layer 3: conv(hA) -> out (no epilogue)
    k_spmm<<<spmm_blocks, 256>>>(hA);
    k_gemm<<<gemm_blocks, 256, GEMM_SMEM_BYTES>>>(hA, W_rel + 3 * 128 * 128, W_root + 3 * 128 * 128,
                                                  b_rel + 3 * 128, gamma, beta, out, 2);
}

// round 4
// speedup vs baseline: 1.9256x; 1.7045x over previous
#include <cuda_runtime.h>
#include <cuda_bf16.h>
#include <cstdint>

#define NNODES 100000
#define DIM 128
#define MAXEDGE 1700000

typedef unsigned int uint;

// ---------------- device scratch (static, no allocation) ----------------
__device__ float g_hA[NNODES * DIM];
__device__ float g_hB[NNODES * DIM];
__device__ float g_agg[NNODES * DIM];
__device__ int   g_cnt[NNODES];
__device__ int   g_tmp[NNODES];
__device__ int   g_rowptr[NNODES + 1];
__device__ int   g_cursor[NNODES];
__device__ int   g_col[MAXEDGE];
__device__ int   g_part[256];
__device__ int   g_partscan[256];

// ---------------- helpers ----------------
__device__ __forceinline__ uint32_t smem_u32(const void* p) {
    uint32_t a;
    asm("{ .reg .u64 t; cvta.to.shared.u64 t, %1; cvt.u32.u64 %0, t; }" : "=r"(a) : "l"(p));
    return a;
}
__device__ __forceinline__ void ldsm4(uint32_t addr, uint32_t& r0, uint32_t& r1,
                                      uint32_t& r2, uint32_t& r3) {
    asm volatile("ldmatrix.sync.aligned.m8n8.x4.shared.b16 {%0,%1,%2,%3}, [%4];"
                 : "=r"(r0), "=r"(r1), "=r"(r2), "=r"(r3) : "r"(addr));
}
__device__ __forceinline__ void ldsm4t(uint32_t addr, uint32_t& r0, uint32_t& r1,
                                       uint32_t& r2, uint32_t& r3) {
    asm volatile("ldmatrix.sync.aligned.m8n8.x4.trans.shared.b16 {%0,%1,%2,%3}, [%4];"
                 : "=r"(r0), "=r"(r1), "=r"(r2), "=r"(r3) : "r"(addr));
}
__device__ __forceinline__ void mma_bf16(float* c, uint32_t a0, uint32_t a1,
                                         uint32_t a2, uint32_t a3,
                                         uint32_t b0, uint32_t b1) {
    asm volatile("mma.sync.aligned.m16n8k16.row.col.f32.bf16.bf16.f32 "
                 "{%0,%1,%2,%3}, {%4,%5,%6,%7}, {%8,%9}, {%0,%1,%2,%3};"
                 : "+f"(c[0]), "+f"(c[1]), "+f"(c[2]), "+f"(c[3])
                 : "r"(a0), "r"(a1), "r"(a2), "r"(a3), "r"(b0), "r"(b1));
}
// split two fp32 -> packed bf16 hi-pair + lo-pair
__device__ __forceinline__ void split2(float x, float y, uint& hp, uint& lp) {
    __nv_bfloat16 hx = __float2bfloat16(x), hy = __float2bfloat16(y);
    float rx = x - __bfloat162float(hx);
    float ry = y - __bfloat162float(hy);
    __nv_bfloat16 lx = __float2bfloat16(rx), ly = __float2bfloat16(ry);
    hp = ((uint)__bfloat16_as_ushort(hy) << 16) | (uint)__bfloat16_as_ushort(hx);
    lp = ((uint)__bfloat16_as_ushort(ly) << 16) | (uint)__bfloat16_as_ushort(lx);
}

// ---------------- CSR build ----------------
__global__ void k_zero_cnt() {
    int i = blockIdx.x * blockDim.x + threadIdx.x;
    if (i < NNODES) g_cnt[i] = 0;
}
__global__ void k_hist(const int* __restrict__ dst, int E) {
    int e = blockIdx.x * blockDim.x + threadIdx.x;
    if (e < E) atomicAdd(&g_cnt[dst[e]], 1);
}
__global__ void k_scan1() {
    __shared__ int s[512];
    int t = threadIdx.x;
    int i = blockIdx.x * 512 + t;
    int v = (i < NNODES) ? g_cnt[i] : 0;
    s[t] = v;
    __syncthreads();
#pragma unroll
    for (int off = 1; off < 512; off <<= 1) {
        int x = (t >= off) ? s[t - off] : 0;
        __syncthreads();
        s[t] += x;
        __syncthreads();
    }
    if (i < NNODES) g_tmp[i] = s[t] - v;
    if (t == 511) g_part[blockIdx.x] = s[511];
}
__global__ void k_scan2(int nblocks) {
    __shared__ int s[256];
    int t = threadIdx.x;
    int v = (t < nblocks) ? g_part[t] : 0;
    s[t] = v;
    __syncthreads();
#pragma unroll
    for (int off = 1; off < 256; off <<= 1) {
        int x = (t >= off) ? s[t - off] : 0;
        __syncthreads();
        s[t] += x;
        __syncthreads();
    }
    g_partscan[t] = s[t] - v;
}
__global__ void k_scan3(int E) {
    int i = blockIdx.x * blockDim.x + threadIdx.x;
    if (i < NNODES) {
        int r = g_tmp[i] + g_partscan[i >> 9];
        g_rowptr[i] = r;
        g_cursor[i] = r;
    }
    if (i == 0) g_rowptr[NNODES] = E;
}
__global__ void k_scatter(const int* __restrict__ src, const int* __restrict__ dst, int E) {
    int e = blockIdx.x * blockDim.x + threadIdx.x;
    if (e < E) {
        int p = atomicAdd(&g_cursor[dst[e]], 1);
        g_col[p] = src[e];
    }
}

// ---------------- SpMM ----------------
__global__ void __launch_bounds__(256) k_spmm(const float* __restrict__ h) {
    int gw = (blockIdx.x * blockDim.x + threadIdx.x) >> 5;
    if (gw >= NNODES) return;
    int lane = threadIdx.x & 31;
    int s = g_rowptr[gw];
    int e = g_rowptr[gw + 1];
    const float4* hv = (const float4*)h;
    float4 acc = make_float4(0.f, 0.f, 0.f, 0.f);
    int i = s;
    for (; i + 4 <= e; i += 4) {
        int n0 = g_col[i], n1 = g_col[i + 1], n2 = g_col[i + 2], n3 = g_col[i + 3];
        float4 a = __ldg(&hv[n0 * 32 + lane]);
        float4 b = __ldg(&hv[n1 * 32 + lane]);
        float4 c = __ldg(&hv[n2 * 32 + lane]);
        float4 d = __ldg(&hv[n3 * 32 + lane]);
        acc.x += (a.x + b.x) + (c.x + d.x);
        acc.y += (a.y + b.y) + (c.y + d.y);
        acc.z += (a.z + b.z) + (c.z + d.z);
        acc.w += (a.w + b.w) + (c.w + d.w);
    }
    for (; i < e; i++) {
        int n = g_col[i];
        float4 a = __ldg(&hv[n * 32 + lane]);
        acc.x += a.x; acc.y += a.y; acc.z += a.z; acc.w += a.w;
    }
    ((float4*)g_agg)[gw * 32 + lane] = acc;
}

// ---------------- tensor-core GEMM (mma.sync bf16, 3-split) + fused epilogue ----
// out[128x128 tile] = agg@Wrel + bias + hin@Wroot, then
// mode 0: ReLU+LN ; 1: +residual, ReLU+LN ; 2: plain.
#define LDK 136                       // padded bf16 row length (272 B = 17 x 16B)
#define OFF_AHI 0
#define OFF_ALO (OFF_AHI + 128 * LDK * 2)
#define OFF_WHI (OFF_ALO + 128 * LDK * 2)
#define OFF_WLO (OFF_WHI + 128 * LDK * 2)
#define GSM_TOTAL (OFF_WLO + 128 * LDK * 2)
#define LDC 132                       // fp32 C tile padded width
#define OFF_MEAN (OFF_WHI)            // aliases dead W region after mainloop
#define OFF_RS   (OFF_WHI + 512)

__global__ void __launch_bounds__(256, 1) k_gemm_mma(
    const float* __restrict__ hin,
    const float* __restrict__ Wrel, const float* __restrict__ Wroot,
    const float* __restrict__ bias,
    const float* __restrict__ gamma, const float* __restrict__ beta,
    float* __restrict__ hout, int mode)
{
    extern __shared__ char smem[];
    uint32_t sb = smem_u32(smem);
    int tid = threadIdx.x;
    int wid = tid >> 5;
    int lane = tid & 31;
    int wr = wid & 3;        // warp row (0..3) -> rows wr*32..+31
    int wc = wid >> 2;       // warp col (0..1) -> cols wc*64..+63
    int lane15 = lane & 15;
    int laneHi = lane >> 4;
    int rowBase = blockIdx.x * 128;

    float acc[2][8][4];
#pragma unroll
    for (int mt = 0; mt < 2; mt++)
#pragma unroll
        for (int nt = 0; nt < 8; nt++)
#pragma unroll
            for (int q = 0; q < 4; q++) acc[mt][nt][q] = 0.f;

    for (int srci = 0; srci < 2; srci++) {
        // ---- stage A (activations) fp32 -> bf16 hi/lo ----
        const float4* src4 = (const float4*)(srci ? hin : g_agg);
        for (int i = tid; i < 4096; i += 256) {
            int r = i >> 5, c4 = i & 31;
            int grow = rowBase + r;
            float4 v = make_float4(0.f, 0.f, 0.f, 0.f);
            if (grow < NNODES) v = __ldg(&src4[grow * 32 + c4]);
            uint h0, l0, h1, l1;
            split2(v.x, v.y, h0, l0);
            split2(v.z, v.w, h1, l1);
            int idx = r * LDK + c4 * 4;   // bf16 index, byte = idx*2 (8B aligned)
            *(uint2*)(smem + OFF_AHI + idx * 2) = make_uint2(h0, h1);
            *(uint2*)(smem + OFF_ALO + idx * 2) = make_uint2(l0, l1);
        }
        // ---- stage W [k][n] fp32 -> bf16 hi/lo ----
        const float4* w4 = (const float4*)(srci ? Wroot : Wrel);
        for (int i = tid; i < 4096; i += 256) {
            int k = i >> 5, n4 = i & 31;
            float4 v = __ldg(&w4[k * 32 + n4]);
            uint h0, l0, h1, l1;
            split2(v.x, v.y, h0, l0);
            split2(v.z, v.w, h1, l1);
            int idx = k * LDK + n4 * 4;
            *(uint2*)(smem + OFF_WHI + idx * 2) = make_uint2(h0, h1);
            *(uint2*)(smem + OFF_WLO + idx * 2) = make_uint2(l0, l1);
        }
        __syncthreads();

        // ---- 3 split passes ----
#pragma unroll
        for (int pass = 0; pass < 3; pass++) {
            uint32_t abase = sb + (pass == 2 ? OFF_ALO : OFF_AHI);
            uint32_t wbase = sb + (pass == 1 ? OFF_WLO : OFF_WHI);
            // per-lane ldmatrix base addresses
            uint32_t aAddr0 = abase + ((wr * 32 + lane15) * LDK + laneHi * 8) * 2;
            uint32_t wAddr0 = wbase + (lane15 * LDK + wc * 64 + laneHi * 8) * 2;
#pragma unroll
            for (int ks = 0; ks < 8; ks++) {
                uint32_t A0[4], A1[4];
                uint32_t aAddr = aAddr0 + ks * 32;            // +k0*2 bytes
                ldsm4(aAddr, A0[0], A0[1], A0[2], A0[3]);
                ldsm4(aAddr + 16 * LDK * 2, A1[0], A1[1], A1[2], A1[3]);
                uint32_t wAddr = wAddr0 + ks * 16 * LDK * 2;  // +k0 rows
#pragma unroll
                for (int g = 0; g < 4; g++) {
                    uint32_t b0, b1, b2, b3;
                    ldsm4t(wAddr + g * 32, b0, b1, b2, b3);
                    mma_bf16(acc[0][2 * g],     A0[0], A0[1], A0[2], A0[3], b0, b1);
                    mma_bf16(acc[0][2 * g + 1], A0[0], A0[1], A0[2], A0[3], b2, b3);
                    mma_bf16(acc[1][2 * g],     A1[0], A1[1], A1[2], A1[3], b0, b1);
                    mma_bf16(acc[1][2 * g + 1], A1[0], A1[1], A1[2], A1[3], b2, b3);
                }
            }
        }
        __syncthreads();   // before restage (srci=0) / before C spill (srci=1)
    }

    // ---- spill accumulators to fp32 smem tile (aliases A region) ----
    float* sC = (float*)smem;
    {
        int r0 = wr * 32 + (lane >> 2);
        int c0 = wc * 64 + (lane & 3) * 2;
#pragma unroll
        for (int mt = 0; mt < 2; mt++)
#pragma unroll
            for (int nt = 0; nt < 8; nt++) {
                int r = r0 + mt * 16;
                int c = c0 + nt * 8;
                sC[r * LDC + c]           = acc[mt][nt][0];
                sC[r * LDC + c + 1]       = acc[mt][nt][1];
                sC[(r + 8) * LDC + c]     = acc[mt][nt][2];
                sC[(r + 8) * LDC + c + 1] = acc[mt][nt][3];
            }
    }
    __syncthreads();

    float* sMean = (float*)(smem + OFF_MEAN);
    float* sRs   = (float*)(smem + OFF_RS);

    // ---- E1: bias/residual/ReLU + row stats (2 threads per row) ----
    if (mode != 2) {
        int r = tid >> 1, h = tid & 1;
        int grow = rowBase + r;
        float s1 = 0.f, s2 = 0.f;
        const float4* b4 = (const float4*)bias;
        const float4* h4 = (const float4*)hin;
#pragma unroll
        for (int j = 0; j < 16; j++) {
            int c4 = h * 16 + j;
            float4 x = *(float4*)&sC[r * LDC + c4 * 4];
            float4 b = __ldg(&b4[c4]);
            x.x += b.x; x.y += b.y; x.z += b.z; x.w += b.w;
            if (mode == 1 && grow < NNODES) {
                float4 hv = __ldg(&h4[grow * 32 + c4]);
                x.x += hv.x; x.y += hv.y; x.z += hv.z; x.w += hv.w;
            }
            x.x = fmaxf(x.x, 0.f); x.y = fmaxf(x.y, 0.f);
            x.z = fmaxf(x.z, 0.f); x.w = fmaxf(x.w, 0.f);
            *(float4*)&sC[r * LDC + c4 * 4] = x;
            s1 += (x.x + x.y) + (x.z + x.w);
            s2 += (x.x * x.x + x.y * x.y) + (x.z * x.z + x.w * x.w);
        }
        s1 += __shfl_xor_sync(0xffffffffu, s1, 1);
        s2 += __shfl_xor_sync(0xffffffffu, s2, 1);
        if (h == 0) {
            float mean = s1 * (1.0f / 128.0f);
            float var  = s2 * (1.0f / 128.0f) - mean * mean;
            sMean[r] = mean;
            sRs[r]   = rsqrtf(var + 1e-5f);
        }
    }
    __syncthreads();

    // ---- E2: coalesced LN-apply (or bias-add) + store ----
    {
        float4 gv  = __ldg(&((const float4*)gamma)[lane]);
        float4 btv = __ldg(&((const float4*)beta)[lane]);
        float4 bv  = __ldg(&((const float4*)bias)[lane]);
        float4* o4 = (float4*)hout;
#pragma unroll
        for (int p = 0; p < 16; p++) {
            int r = p * 8 + wid;
            int grow = rowBase + r;
            if (grow >= NNODES) continue;
            float4 x = *(float4*)&sC[r * LDC + lane * 4];
            if (mode != 2) {
                float mean = sMean[r], rs = sRs[r];
                x.x = (x.x - mean) * rs * gv.x + btv.x;
                x.y = (x.y - mean) * rs * gv.y + btv.y;
                x.z = (x.z - mean) * rs * gv.z + btv.z;
                x.w = (x.w - mean) * rs * gv.w + btv.w;
            } else {
                x.x += bv.x; x.y += bv.y; x.z += bv.z; x.w += bv.w;
            }
            o4[grow * 32 + lane] = x;
        }
    }
}

// ---------------- host ----------------
extern "C" void kernel_launch(void* const* d_in, const int* in_sizes, int n_in,
                              void* d_out, int out_size)
{
    const float* in_feat = (const float*)d_in[0];
    const int*   eidx    = (const int*)d_in[1];
    const float* W_rel   = (const float*)d_in[2];
    const float* b_rel   = (const float*)d_in[3];
    const float* W_root  = (const float*)d_in[4];
    const float* gamma   = (const float*)d_in[5];
    const float* beta    = (const float*)d_in[6];
    float* out = (float*)d_out;

    int E = in_sizes[1] / 2;
    const int* src = eidx;
    const int* dst = eidx + E;

    float *hA, *hB;
    cudaGetSymbolAddress((void**)&hA, g_hA);
    cudaGetSymbolAddress((void**)&hB, g_hB);

    cudaFuncSetAttribute(k_gemm_mma, cudaFuncAttributeMaxDynamicSharedMemorySize, GSM_TOTAL);

    int nb_nodes = (NNODES + 255) / 256;
    int nb_edges = (E + 255) / 256;
    int nb_scan  = (NNODES + 511) / 512;

    // CSR build
    k_zero_cnt<<<nb_nodes, 256>>>();
    k_hist<<<nb_edges, 256>>>(dst, E);
    k_scan1<<<nb_scan, 512>>>();
    k_scan2<<<1, 256>>>(nb_scan);
    k_scan3<<<nb_nodes, 256>>>(E);
    k_scatter<<<nb_edges, 256>>>(src, dst, E);

    int spmm_blocks = (NNODES * 32 + 255) / 256;
    int gemm_blocks = (NNODES + 127) / 128;

    // layer 0
    k_spmm<<<spmm_blocks, 256>>>(in_feat);
    k_gemm_mma<<<gemm_blocks, 256, GSM_TOTAL>>>(in_feat, W_rel, W_root, b_rel,
                                                gamma, beta, hA, 0);
    // layer 1
    k_spmm<<<spmm_blocks, 256>>>(hA);
    k_gemm_mma<<<gemm_blocks, 256, GSM_TOTAL>>>(hA, W_rel + 16384, W_root + 16384,
                                                b_rel + 128, gamma, beta, hB, 1);
    // layer 2
    k_spmm<<<spmm_blocks, 256>>>(hB);
    k_gemm_mma<<<gemm_blocks, 256, GSM_TOTAL>>>(hB, W_rel + 32768, W_root + 32768,
                                                b_rel + 256, gamma, beta, hA, 1);
    // layer 3 (no epilogue)
    k_spmm<<<spmm_blocks, 256>>>(hA);
    k_gemm_mma<<<gemm_blocks, 256, GSM_TOTAL>>>(hA, W_rel + 49152, W_root + 49152,
                                                b_rel + 384, gamma, beta, out, 2);
}

// round 5
// speedup vs baseline: 1.9271x; 1.0008x over previous
#include <cuda_runtime.h>
#include <cuda_bf16.h>
#include <cstdint>

#define NNODES 100000
#define DIM 128
#define MAXEDGE 1700000

typedef unsigned int uint;

// ---------------- device scratch (static, no allocation) ----------------
__device__ float g_hA[NNODES * DIM];
__device__ float g_hB[NNODES * DIM];
__device__ float g_agg[NNODES * DIM];
__device__ int   g_cnt[NNODES];
__device__ int   g_tmp[NNODES];
__device__ int   g_rowptr[NNODES + 1];
__device__ int   g_cursor[NNODES];
__device__ int   g_col[MAXEDGE];
__device__ int   g_part[256];
__device__ int   g_partscan[256];
// pre-split weights: [layer][mat][hilo] x 128x128 bf16 (unpadded row-major [k][n])
__device__ unsigned short g_Wbf[4 * 2 * 2 * 16384];

// ---------------- helpers ----------------
__device__ __forceinline__ uint32_t smem_u32(const void* p) {
    uint32_t a;
    asm("{ .reg .u64 t; cvta.to.shared.u64 t, %1; cvt.u32.u64 %0, t; }" : "=r"(a) : "l"(p));
    return a;
}
__device__ __forceinline__ void ldsm4(uint32_t addr, uint32_t& r0, uint32_t& r1,
                                      uint32_t& r2, uint32_t& r3) {
    asm volatile("ldmatrix.sync.aligned.m8n8.x4.shared.b16 {%0,%1,%2,%3}, [%4];"
                 : "=r"(r0), "=r"(r1), "=r"(r2), "=r"(r3) : "r"(addr));
}
__device__ __forceinline__ void ldsm4t(uint32_t addr, uint32_t& r0, uint32_t& r1,
                                       uint32_t& r2, uint32_t& r3) {
    asm volatile("ldmatrix.sync.aligned.m8n8.x4.trans.shared.b16 {%0,%1,%2,%3}, [%4];"
                 : "=r"(r0), "=r"(r1), "=r"(r2), "=r"(r3) : "r"(addr));
}
__device__ __forceinline__ void mma_bf16(float* c, uint32_t a0, uint32_t a1,
                                         uint32_t a2, uint32_t a3,
                                         uint32_t b0, uint32_t b1) {
    asm volatile("mma.sync.aligned.m16n8k16.row.col.f32.bf16.bf16.f32 "
                 "{%0,%1,%2,%3}, {%4,%5,%6,%7}, {%8,%9}, {%0,%1,%2,%3};"
                 : "+f"(c[0]), "+f"(c[1]), "+f"(c[2]), "+f"(c[3])
                 : "r"(a0), "r"(a1), "r"(a2), "r"(a3), "r"(b0), "r"(b1));
}
// split two fp32 -> packed bf16 hi-pair + lo-pair
__device__ __forceinline__ void split2(float x, float y, uint& hp, uint& lp) {
    __nv_bfloat16 hx = __float2bfloat16(x), hy = __float2bfloat16(y);
    float rx = x - __bfloat162float(hx);
    float ry = y - __bfloat162float(hy);
    __nv_bfloat16 lx = __float2bfloat16(rx), ly = __float2bfloat16(ry);
    hp = ((uint)__bfloat16_as_ushort(hy) << 16) | (uint)__bfloat16_as_ushort(hx);
    lp = ((uint)__bfloat16_as_ushort(ly) << 16) | (uint)__bfloat16_as_ushort(lx);
}

// ---------------- CSR build ----------------
__global__ void k_hist(const int* __restrict__ dst, int E) {
    int e = blockIdx.x * blockDim.x + threadIdx.x;
    if (e < E) atomicAdd(&g_cnt[dst[e]], 1);
}
__global__ void k_scan1() {
    __shared__ int s[512];
    int t = threadIdx.x;
    int i = blockIdx.x * 512 + t;
    int v = (i < NNODES) ? g_cnt[i] : 0;
    s[t] = v;
    __syncthreads();
#pragma unroll
    for (int off = 1; off < 512; off <<= 1) {
        int x = (t >= off) ? s[t - off] : 0;
        __syncthreads();
        s[t] += x;
        __syncthreads();
    }
    if (i < NNODES) g_tmp[i] = s[t] - v;
    if (t == 511) g_part[blockIdx.x] = s[511];
}
__global__ void k_scan2(int nblocks) {
    __shared__ int s[256];
    int t = threadIdx.x;
    int v = (t < nblocks) ? g_part[t] : 0;
    s[t] = v;
    __syncthreads();
#pragma unroll
    for (int off = 1; off < 256; off <<= 1) {
        int x = (t >= off) ? s[t - off] : 0;
        __syncthreads();
        s[t] += x;
        __syncthreads();
    }
    g_partscan[t] = s[t] - v;
}
__global__ void k_scan3(int E) {
    int i = blockIdx.x * blockDim.x + threadIdx.x;
    if (i < NNODES) {
        int r = g_tmp[i] + g_partscan[i >> 9];
        g_rowptr[i] = r;
        g_cursor[i] = r;
    }
    if (i == 0) g_rowptr[NNODES] = E;
}
__global__ void k_scatter(const int* __restrict__ src, const int* __restrict__ dst, int E) {
    int e = blockIdx.x * blockDim.x + threadIdx.x;
    if (e < E) {
        int p = atomicAdd(&g_cursor[dst[e]], 1);
        g_col[p] = src[e];
    }
}

// ---------------- SpMM: agg[i,:] = sum_{j in adj(i)} h[j,:] -------------
__global__ void __launch_bounds__(256) k_spmm(const float* __restrict__ h) {
    int gw = (blockIdx.x * blockDim.x + threadIdx.x) >> 5;
    if (gw >= NNODES) return;
    int lane = threadIdx.x & 31;
    int s = g_rowptr[gw];
    int e = g_rowptr[gw + 1];
    const float4* hv = (const float4*)h;
    float4 accA = make_float4(0.f, 0.f, 0.f, 0.f);
    float4 accB = make_float4(0.f, 0.f, 0.f, 0.f);
    int i = s;
    for (; i + 8 <= e; i += 8) {
        int n0 = g_col[i],     n1 = g_col[i + 1], n2 = g_col[i + 2], n3 = g_col[i + 3];
        int n4 = g_col[i + 4], n5 = g_col[i + 5], n6 = g_col[i + 6], n7 = g_col[i + 7];
        float4 a = __ldg(&hv[n0 * 32 + lane]);
        float4 b = __ldg(&hv[n1 * 32 + lane]);
        float4 c = __ldg(&hv[n2 * 32 + lane]);
        float4 d = __ldg(&hv[n3 * 32 + lane]);
        float4 p = __ldg(&hv[n4 * 32 + lane]);
        float4 q = __ldg(&hv[n5 * 32 + lane]);
        float4 r = __ldg(&hv[n6 * 32 + lane]);
        float4 t = __ldg(&hv[n7 * 32 + lane]);
        accA.x += (a.x + b.x) + (c.x + d.x);
        accA.y += (a.y + b.y) + (c.y + d.y);
        accA.z += (a.z + b.z) + (c.z + d.z);
        accA.w += (a.w + b.w) + (c.w + d.w);
        accB.x += (p.x + q.x) + (r.x + t.x);
        accB.y += (p.y + q.y) + (r.y + t.y);
        accB.z += (p.z + q.z) + (r.z + t.z);
        accB.w += (p.w + q.w) + (r.w + t.w);
    }
    for (; i + 4 <= e; i += 4) {
        int n0 = g_col[i], n1 = g_col[i + 1], n2 = g_col[i + 2], n3 = g_col[i + 3];
        float4 a = __ldg(&hv[n0 * 32 + lane]);
        float4 b = __ldg(&hv[n1 * 32 + lane]);
        float4 c = __ldg(&hv[n2 * 32 + lane]);
        float4 d = __ldg(&hv[n3 * 32 + lane]);
        accA.x += (a.x + b.x) + (c.x + d.x);
        accA.y += (a.y + b.y) + (c.y + d.y);
        accA.z += (a.z + b.z) + (c.z + d.z);
        accA.w += (a.w + b.w) + (c.w + d.w);
    }
    for (; i < e; i++) {
        int n = g_col[i];
        float4 a = __ldg(&hv[n * 32 + lane]);
        accA.x += a.x; accA.y += a.y; accA.z += a.z; accA.w += a.w;
    }
    accA.x += accB.x; accA.y += accB.y; accA.z += accB.z; accA.w += accB.w;
    ((float4*)g_agg)[gw * 32 + lane] = accA;
}

// ---------------- W pre-split (once per launch) ----------------
__global__ void k_wsplit(const float* __restrict__ Wrel, const float* __restrict__ Wroot) {
    int l = blockIdx.x >> 1, m = blockIdx.x & 1;
    const float* W = (m ? Wroot : Wrel) + l * 16384;
    unsigned short* hip = g_Wbf + ((l * 2 + m) * 2) * 16384;
    unsigned short* lop = hip + 16384;
    for (int idx = threadIdx.x; idx < 16384; idx += blockDim.x) {
        float w = W[idx];
        __nv_bfloat16 h = __float2bfloat16(w);
        float r = w - __bfloat162float(h);
        hip[idx] = __bfloat16_as_ushort(h);
        lop[idx] = __bfloat16_as_ushort(__float2bfloat16(r));
    }
}

// ---------------- tensor-core GEMM (mma.sync bf16, 3-split) + fused epilogue ----
#define LDK 136                       // padded bf16 row length (272 B)
#define TILE (128 * LDK * 2)          // 34816 B
#define OFF_AHI 0
#define OFF_ALO TILE
#define OFF_W   (2 * TILE)            // 4 W tiles: [rel hi][rel lo][root hi][root lo]
#define GSM_TOTAL (6 * TILE)          // 208896 B
#define LDC 132
#define OFF_MEAN OFF_W                // aliases dead W region after mainloop
#define OFF_RS   (OFF_W + 512)

__global__ void __launch_bounds__(256, 1) k_gemm_mma(
    const float* __restrict__ hin, int layer,
    const float* __restrict__ bias,
    const float* __restrict__ gamma, const float* __restrict__ beta,
    float* __restrict__ hout, int mode)
{
    extern __shared__ char smem[];
    uint32_t sb = smem_u32(smem);
    int tid = threadIdx.x;
    int wid = tid >> 5;
    int lane = tid & 31;
    int wr = wid & 3;
    int wc = wid >> 2;
    int lane15 = lane & 15;
    int laneHi = lane >> 4;
    int rowBase = blockIdx.x * 128;

    // ---- stage all 4 pre-split W tiles (plain copies, padded rows) ----
    {
        const uint4* wsrc = (const uint4*)(g_Wbf + layer * 4 * 16384);
        for (int tI = 0; tI < 4; tI++) {
            char* dbase = smem + OFF_W + tI * TILE;
            const uint4* sbase = wsrc + tI * 2048;
            for (int i = tid; i < 2048; i += 256) {
                int r = i >> 4, q = i & 15;
                *(uint4*)(dbase + r * (LDK * 2) + q * 16) = __ldg(&sbase[i]);
            }
        }
    }

    float acc[2][8][4];
#pragma unroll
    for (int mt = 0; mt < 2; mt++)
#pragma unroll
        for (int nt = 0; nt < 8; nt++)
#pragma unroll
            for (int q = 0; q < 4; q++) acc[mt][nt][q] = 0.f;

    for (int srci = 0; srci < 2; srci++) {
        // ---- stage A (activations) fp32 -> bf16 hi/lo ----
        const float4* src4 = (const float4*)(srci ? hin : g_agg);
        for (int i = tid; i < 4096; i += 256) {
            int r = i >> 5, c4 = i & 31;
            int grow = rowBase + r;
            float4 v = make_float4(0.f, 0.f, 0.f, 0.f);
            if (grow < NNODES) v = __ldg(&src4[grow * 32 + c4]);
            uint h0, l0, h1, l1;
            split2(v.x, v.y, h0, l0);
            split2(v.z, v.w, h1, l1);
            int idx = r * LDK + c4 * 4;
            *(uint2*)(smem + OFF_AHI + idx * 2) = make_uint2(h0, h1);
            *(uint2*)(smem + OFF_ALO + idx * 2) = make_uint2(l0, l1);
        }
        __syncthreads();

        // ---- 3 split passes ----
#pragma unroll
        for (int pass = 0; pass < 3; pass++) {
            uint32_t abase = sb + (pass == 2 ? OFF_ALO : OFF_AHI);
            uint32_t wbase = sb + OFF_W + srci * 2 * TILE + (pass == 1 ? TILE : 0);
            uint32_t aAddr0 = abase + ((wr * 32 + lane15) * LDK + laneHi * 8) * 2;
            uint32_t wAddr0 = wbase + (lane15 * LDK + wc * 64 + laneHi * 8) * 2;
#pragma unroll
            for (int ks = 0; ks < 8; ks++) {
                uint32_t A0[4], A1[4];
                uint32_t aAddr = aAddr0 + ks * 32;
                ldsm4(aAddr, A0[0], A0[1], A0[2], A0[3]);
                ldsm4(aAddr + 16 * LDK * 2, A1[0], A1[1], A1[2], A1[3]);
                uint32_t wAddr = wAddr0 + ks * 16 * LDK * 2;
#pragma unroll
                for (int g = 0; g < 4; g++) {
                    uint32_t b0, b1, b2, b3;
                    ldsm4t(wAddr + g * 32, b0, b1, b2, b3);
                    mma_bf16(acc[0][2 * g],     A0[0], A0[1], A0[2], A0[3], b0, b1);
                    mma_bf16(acc[0][2 * g + 1], A0[0], A0[1], A0[2], A0[3], b2, b3);
                    mma_bf16(acc[1][2 * g],     A1[0], A1[1], A1[2], A1[3], b0, b1);
                    mma_bf16(acc[1][2 * g + 1], A1[0], A1[1], A1[2], A1[3], b2, b3);
                }
            }
        }
        __syncthreads();   // before A restage (srci=0) / before C spill (srci=1)
    }

    // ---- spill accumulators to fp32 smem tile (aliases A region) ----
    float* sC = (float*)smem;
    {
        int r0 = wr * 32 + (lane >> 2);
        int c0 = wc * 64 + (lane & 3) * 2;
#pragma unroll
        for (int mt = 0; mt < 2; mt++)
#pragma unroll
            for (int nt = 0; nt < 8; nt++) {
                int r = r0 + mt * 16;
                int c = c0 + nt * 8;
                sC[r * LDC + c]           = acc[mt][nt][0];
                sC[r * LDC + c + 1]       = acc[mt][nt][1];
                sC[(r + 8) * LDC + c]     = acc[mt][nt][2];
                sC[(r + 8) * LDC + c + 1] = acc[mt][nt][3];
            }
    }
    __syncthreads();

    float* sMean = (float*)(smem + OFF_MEAN);
    float* sRs   = (float*)(smem + OFF_RS);

    // ---- E1: bias/residual/ReLU + row stats (2 threads per row) ----
    if (mode != 2) {
        int r = tid >> 1, h = tid & 1;
        int grow = rowBase + r;
        float s1 = 0.f, s2 = 0.f;
        const float4* b4 = (const float4*)bias;
        const float4* h4 = (const float4*)hin;
#pragma unroll
        for (int j = 0; j < 16; j++) {
            int c4 = h * 16 + j;
            float4 x = *(float4*)&sC[r * LDC + c4 * 4];
            float4 b = __ldg(&b4[c4]);
            x.x += b.x; x.y += b.y; x.z += b.z; x.w += b.w;
            if (mode == 1 && grow < NNODES) {
                float4 hv = __ldg(&h4[grow * 32 + c4]);
                x.x += hv.x; x.y += hv.y; x.z += hv.z; x.w += hv.w;
            }
            x.x = fmaxf(x.x, 0.f); x.y = fmaxf(x.y, 0.f);
            x.z = fmaxf(x.z, 0.f); x.w = fmaxf(x.w, 0.f);
            *(float4*)&sC[r * LDC + c4 * 4] = x;
            s1 += (x.x + x.y) + (x.z + x.w);
            s2 += (x.x * x.x + x.y * x.y) + (x.z * x.z + x.w * x.w);
        }
        s1 += __shfl_xor_sync(0xffffffffu, s1, 1);
        s2 += __shfl_xor_sync(0xffffffffu, s2, 1);
        if (h == 0) {
            float mean = s1 * (1.0f / 128.0f);
            float var  = s2 * (1.0f / 128.0f) - mean * mean;
            sMean[r] = mean;
            sRs[r]   = rsqrtf(var + 1e-5f);
        }
    }
    __syncthreads();

    // ---- E2: coalesced LN-apply (or bias-add) + store ----
    {
        float4 gv  = __ldg(&((const float4*)gamma)[lane]);
        float4 btv = __ldg(&((const float4*)beta)[lane]);
        float4 bv  = __ldg(&((const float4*)bias)[lane]);
        float4* o4 = (float4*)hout;
#pragma unroll
        for (int p = 0; p < 16; p++) {
            int r = p * 8 + wid;
            int grow = rowBase + r;
            if (grow >= NNODES) continue;
            float4 x = *(float4*)&sC[r * LDC + lane * 4];
            if (mode != 2) {
                float mean = sMean[r], rs = sRs[r];
                x.x = (x.x - mean) * rs * gv.x + btv.x;
                x.y = (x.y - mean) * rs * gv.y + btv.y;
                x.z = (x.z - mean) * rs * gv.z + btv.z;
                x.w = (x.w - mean) * rs * gv.w + btv.w;
            } else {
                x.x += bv.x; x.y += bv.y; x.z += bv.z; x.w += bv.w;
            }
            o4[grow * 32 + lane] = x;
        }
    }
}

// ---------------- host ----------------
extern "C" void kernel_launch(void* const* d_in, const int* in_sizes, int n_in,
                              void* d_out, int out_size)
{
    const float* in_feat = (const float*)d_in[0];
    const int*   eidx    = (const int*)d_in[1];
    const float* W_rel   = (const float*)d_in[2];
    const float* b_rel   = (const float*)d_in[3];
    const float* W_root  = (const float*)d_in[4];
    const float* gamma   = (const float*)d_in[5];
    const float* beta    = (const float*)d_in[6];
    float* out = (float*)d_out;

    int E = in_sizes[1] / 2;
    const int* src = eidx;
    const int* dst = eidx + E;

    float *hA, *hB;
    cudaGetSymbolAddress((void**)&hA, g_hA);
    cudaGetSymbolAddress((void**)&hB, g_hB);
    int* cntp;
    cudaGetSymbolAddress((void**)&cntp, g_cnt);

    cudaFuncSetAttribute(k_gemm_mma, cudaFuncAttributeMaxDynamicSharedMemorySize, GSM_TOTAL);

    int nb_nodes = (NNODES + 255) / 256;
    int nb_edges = (E + 255) / 256;
    int nb_scan  = (NNODES + 511) / 512;

    // W pre-split (independent of CSR)
    k_wsplit<<<8, 256>>>(W_rel, W_root);

    // CSR build
    cudaMemsetAsync(cntp, 0, NNODES * sizeof(int));
    k_hist<<<nb_edges, 256>>>(dst, E);
    k_scan1<<<nb_scan, 512>>>();
    k_scan2<<<1, 256>>>(nb_scan);
    k_scan3<<<nb_nodes, 256>>>(E);
    k_scatter<<<nb_edges, 256>>>(src, dst, E);

    int spmm_blocks = (NNODES * 32 + 255) / 256;
    int gemm_blocks = (NNODES + 127) / 128;

    // layer 0
    k_spmm<<<spmm_blocks, 256>>>(in_feat);
    k_gemm_mma<<<gemm_blocks, 256, GSM_TOTAL>>>(in_feat, 0, b_rel, gamma, beta, hA, 0);
    // layer 1
    k_spmm<<<spmm_blocks, 256>>>(hA);
    k_gemm_mma<<<gemm_blocks, 256, GSM_TOTAL>>>(hA, 1, b_rel + 128, gamma, beta, hB, 1);
    // layer 2
    k_spmm<<<spmm_blocks, 256>>>(hB);
    k_gemm_mma<<<gemm_blocks, 256, GSM_TOTAL>>>(hB, 2, b_rel + 256, gamma, beta, hA, 1);
    // layer 3 (no epilogue)
    k_spmm<<<spmm_blocks, 256>>>(hA);
    k_gemm_mma<<<gemm_blocks, 256, GSM_TOTAL>>>(hA, 3, b_rel + 384, gamma, beta, out, 2);
}

// round 6
// speedup vs baseline: 1.9350x; 1.0041x over previous
#include <cuda_runtime.h>
#include <cuda_bf16.h>
#include <cstdint>

#define NNODES 100000
#define DIM 128
#define MAXEDGE 1700000

typedef unsigned int uint;

// ---------------- device scratch (static, no allocation) ----------------
__device__ float g_hA[NNODES * DIM];
__device__ float g_hB[NNODES * DIM];
__device__ float g_agg[NNODES * DIM];
__device__ int   g_cnt[NNODES];        // zero-init at load; re-zeroed by k_scan1 each launch
__device__ int   g_tmp[NNODES];
__device__ int   g_rowptr[NNODES + 1];
__device__ int   g_cursor[NNODES];
__device__ int   g_col[MAXEDGE];
__device__ int   g_part[256];
__device__ int   g_partscan[256];
// pre-split weights: [layer][mat][hilo] x 128x128 bf16 (row-major [k][n])
__device__ unsigned short g_Wbf[4 * 2 * 2 * 16384];

// ---------------- helpers ----------------
__device__ __forceinline__ uint32_t smem_u32(const void* p) {
    uint32_t a;
    asm("{ .reg .u64 t; cvta.to.shared.u64 t, %1; cvt.u32.u64 %0, t; }" : "=r"(a) : "l"(p));
    return a;
}
__device__ __forceinline__ float4 ldcg4(const float4* p) {
    float4 v;
    asm volatile("ld.global.cg.v4.f32 {%0,%1,%2,%3}, [%4];"
                 : "=f"(v.x), "=f"(v.y), "=f"(v.z), "=f"(v.w) : "l"(p));
    return v;
}
__device__ __forceinline__ void ldsm4(uint32_t addr, uint32_t& r0, uint32_t& r1,
                                      uint32_t& r2, uint32_t& r3) {
    asm volatile("ldmatrix.sync.aligned.m8n8.x4.shared.b16 {%0,%1,%2,%3}, [%4];"
                 : "=r"(r0), "=r"(r1), "=r"(r2), "=r"(r3) : "r"(addr));
}
__device__ __forceinline__ void ldsm4t(uint32_t addr, uint32_t& r0, uint32_t& r1,
                                       uint32_t& r2, uint32_t& r3) {
    asm volatile("ldmatrix.sync.aligned.m8n8.x4.trans.shared.b16 {%0,%1,%2,%3}, [%4];"
                 : "=r"(r0), "=r"(r1), "=r"(r2), "=r"(r3) : "r"(addr));
}
__device__ __forceinline__ void mma_bf16(float* c, uint32_t a0, uint32_t a1,
                                         uint32_t a2, uint32_t a3,
                                         uint32_t b0, uint32_t b1) {
    asm volatile("mma.sync.aligned.m16n8k16.row.col.f32.bf16.bf16.f32 "
                 "{%0,%1,%2,%3}, {%4,%5,%6,%7}, {%8,%9}, {%0,%1,%2,%3};"
                 : "+f"(c[0]), "+f"(c[1]), "+f"(c[2]), "+f"(c[3])
                 : "r"(a0), "r"(a1), "r"(a2), "r"(a3), "r"(b0), "r"(b1));
}
__device__ __forceinline__ void split2(float x, float y, uint& hp, uint& lp) {
    __nv_bfloat16 hx = __float2bfloat16(x), hy = __float2bfloat16(y);
    float rx = x - __bfloat162float(hx);
    float ry = y - __bfloat162float(hy);
    __nv_bfloat16 lx = __float2bfloat16(rx), ly = __float2bfloat16(ry);
    hp = ((uint)__bfloat16_as_ushort(hy) << 16) | (uint)__bfloat16_as_ushort(hx);
    lp = ((uint)__bfloat16_as_ushort(ly) << 16) | (uint)__bfloat16_as_ushort(lx);
}

// ---------------- CSR build ----------------
__global__ void k_hist(const int* __restrict__ dst, int E) {
    int e = blockIdx.x * blockDim.x + threadIdx.x;
    if (e < E) atomicAdd(&g_cnt[dst[e]], 1);
}
__global__ void k_scan1() {
    __shared__ int s[512];
    int t = threadIdx.x;
    int i = blockIdx.x * 512 + t;
    int v = (i < NNODES) ? g_cnt[i] : 0;
    s[t] = v;
    __syncthreads();
#pragma unroll
    for (int off = 1; off < 512; off <<= 1) {
        int x = (t >= off) ? s[t - off] : 0;
        __syncthreads();
        s[t] += x;
        __syncthreads();
    }
    if (i < NNODES) {
        g_tmp[i] = s[t] - v;
        g_cnt[i] = 0;          // re-zero for next launch (zero-init covers launch 1)
    }
    if (t == 511) g_part[blockIdx.x] = s[511];
}
__global__ void k_scan2(int nblocks) {
    __shared__ int s[256];
    int t = threadIdx.x;
    int v = (t < nblocks) ? g_part[t] : 0;
    s[t] = v;
    __syncthreads();
#pragma unroll
    for (int off = 1; off < 256; off <<= 1) {
        int x = (t >= off) ? s[t - off] : 0;
        __syncthreads();
        s[t] += x;
        __syncthreads();
    }
    g_partscan[t] = s[t] - v;
}
__global__ void k_scan3(int E) {
    int i = blockIdx.x * blockDim.x + threadIdx.x;
    if (i < NNODES) {
        int r = g_tmp[i] + g_partscan[i >> 9];
        g_rowptr[i] = r;
        g_cursor[i] = r;
    }
    if (i == 0) g_rowptr[NNODES] = E;
}
__global__ void k_scatter(const int* __restrict__ src, const int* __restrict__ dst, int E) {
    int e = blockIdx.x * blockDim.x + threadIdx.x;
    if (e < E) {
        int p = atomicAdd(&g_cursor[dst[e]], 1);
        g_col[p] = src[e];
    }
}

// ---------------- SpMM: agg[i,:] = sum_{j in adj(i)} h[j,:] -------------
__global__ void __launch_bounds__(256) k_spmm(const float* __restrict__ h) {
    int gw = (blockIdx.x * blockDim.x + threadIdx.x) >> 5;
    if (gw >= NNODES) return;
    int lane = threadIdx.x & 31;
    int s = g_rowptr[gw];
    int e = g_rowptr[gw + 1];
    const float4* hv = (const float4*)h;
    float4 accA = make_float4(0.f, 0.f, 0.f, 0.f);
    float4 accB = make_float4(0.f, 0.f, 0.f, 0.f);
    int i = s;
    for (; i + 8 <= e; i += 8) {
        int n0 = g_col[i],     n1 = g_col[i + 1], n2 = g_col[i + 2], n3 = g_col[i + 3];
        int n4 = g_col[i + 4], n5 = g_col[i + 5], n6 = g_col[i + 6], n7 = g_col[i + 7];
        float4 a = ldcg4(&hv[n0 * 32 + lane]);
        float4 b = ldcg4(&hv[n1 * 32 + lane]);
        float4 c = ldcg4(&hv[n2 * 32 + lane]);
        float4 d = ldcg4(&hv[n3 * 32 + lane]);
        float4 p = ldcg4(&hv[n4 * 32 + lane]);
        float4 q = ldcg4(&hv[n5 * 32 + lane]);
        float4 r = ldcg4(&hv[n6 * 32 + lane]);
        float4 t = ldcg4(&hv[n7 * 32 + lane]);
        accA.x += (a.x + b.x) + (c.x + d.x);
        accA.y += (a.y + b.y) + (c.y + d.y);
        accA.z += (a.z + b.z) + (c.z + d.z);
        accA.w += (a.w + b.w) + (c.w + d.w);
        accB.x += (p.x + q.x) + (r.x + t.x);
        accB.y += (p.y + q.y) + (r.y + t.y);
        accB.z += (p.z + q.z) + (r.z + t.z);
        accB.w += (p.w + q.w) + (r.w + t.w);
    }
    for (; i + 4 <= e; i += 4) {
        int n0 = g_col[i], n1 = g_col[i + 1], n2 = g_col[i + 2], n3 = g_col[i + 3];
        float4 a = ldcg4(&hv[n0 * 32 + lane]);
        float4 b = ldcg4(&hv[n1 * 32 + lane]);
        float4 c = ldcg4(&hv[n2 * 32 + lane]);
        float4 d = ldcg4(&hv[n3 * 32 + lane]);
        accA.x += (a.x + b.x) + (c.x + d.x);
        accA.y += (a.y + b.y) + (c.y + d.y);
        accA.z += (a.z + b.z) + (c.z + d.z);
        accA.w += (a.w + b.w) + (c.w + d.w);
    }
    for (; i < e; i++) {
        int n = g_col[i];
        float4 a = ldcg4(&hv[n * 32 + lane]);
        accA.x += a.x; accA.y += a.y; accA.z += a.z; accA.w += a.w;
    }
    accA.x += accB.x; accA.y += accB.y; accA.z += accB.z; accA.w += accB.w;
    ((float4*)g_agg)[gw * 32 + lane] = accA;
}

// ---------------- W pre-split (once per launch) ----------------
__global__ void k_wsplit(const float* __restrict__ Wrel, const float* __restrict__ Wroot) {
    int l = blockIdx.x >> 1, m = blockIdx.x & 1;
    const float* W = (m ? Wroot : Wrel) + l * 16384;
    unsigned short* hip = g_Wbf + ((l * 2 + m) * 2) * 16384;
    unsigned short* lop = hip + 16384;
    for (int idx = threadIdx.x; idx < 16384; idx += blockDim.x) {
        float w = W[idx];
        __nv_bfloat16 h = __float2bfloat16(w);
        float r = w - __bfloat162float(h);
        hip[idx] = __bfloat16_as_ushort(h);
        lop[idx] = __bfloat16_as_ushort(__float2bfloat16(r));
    }
}

// ---------------- tensor-core GEMM (mma.sync bf16, 3-split) + fused epilogue ----
#define LDK 136
#define TILE (128 * LDK * 2)          // 34816 B
#define OFF_AHI 0
#define OFF_ALO TILE
#define OFF_W   (2 * TILE)            // [rel hi][rel lo][root hi][root lo]
#define GSM_TOTAL (6 * TILE)          // 208896 B
#define LDC 132
#define OFF_MEAN OFF_W
#define OFF_RS   (OFF_W + 512)

__global__ void __launch_bounds__(256, 1) k_gemm_mma(
    const float* __restrict__ hin, int layer,
    const float* __restrict__ bias,
    const float* __restrict__ gamma, const float* __restrict__ beta,
    float* __restrict__ hout, int mode)
{
    extern __shared__ char smem[];
    uint32_t sb = smem_u32(smem);
    int tid = threadIdx.x;
    int wid = tid >> 5;
    int lane = tid & 31;
    int wr = wid & 3;
    int wc = wid >> 2;
    int lane15 = lane & 15;
    int laneHi = lane >> 4;
    int rowBase = blockIdx.x * 128;

    // stage 4 pre-split W tiles
    {
        const uint4* wsrc = (const uint4*)(g_Wbf + layer * 4 * 16384);
        for (int tI = 0; tI < 4; tI++) {
            char* dbase = smem + OFF_W + tI * TILE;
            const uint4* sbase = wsrc + tI * 2048;
            for (int i = tid; i < 2048; i += 256) {
                int r = i >> 4, q = i & 15;
                *(uint4*)(dbase + r * (LDK * 2) + q * 16) = __ldg(&sbase[i]);
            }
        }
    }

    float acc[2][8][4];
#pragma unroll
    for (int mt = 0; mt < 2; mt++)
#pragma unroll
        for (int nt = 0; nt < 8; nt++)
#pragma unroll
            for (int q = 0; q < 4; q++) acc[mt][nt][q] = 0.f;

    for (int srci = 0; srci < 2; srci++) {
        const float4* src4 = (const float4*)(srci ? hin : g_agg);
        for (int i = tid; i < 4096; i += 256) {
            int r = i >> 5, c4 = i & 31;
            int grow = rowBase + r;
            float4 v = make_float4(0.f, 0.f, 0.f, 0.f);
            if (grow < NNODES) v = __ldg(&src4[grow * 32 + c4]);
            uint h0, l0, h1, l1;
            split2(v.x, v.y, h0, l0);
            split2(v.z, v.w, h1, l1);
            int idx = r * LDK + c4 * 4;
            *(uint2*)(smem + OFF_AHI + idx * 2) = make_uint2(h0, h1);
            *(uint2*)(smem + OFF_ALO + idx * 2) = make_uint2(l0, l1);
        }
        __syncthreads();

#pragma unroll
        for (int pass = 0; pass < 3; pass++) {
            uint32_t abase = sb + (pass == 2 ? OFF_ALO : OFF_AHI);
            uint32_t wbase = sb + OFF_W + srci * 2 * TILE + (pass == 1 ? TILE : 0);
            uint32_t aAddr0 = abase + ((wr * 32 + lane15) * LDK + laneHi * 8) * 2;
            uint32_t wAddr0 = wbase + (lane15 * LDK + wc * 64 + laneHi * 8) * 2;
#pragma unroll
            for (int ks = 0; ks < 8; ks++) {
                uint32_t A0[4], A1[4];
                uint32_t aAddr = aAddr0 + ks * 32;
                ldsm4(aAddr, A0[0], A0[1], A0[2], A0[3]);
                ldsm4(aAddr + 16 * LDK * 2, A1[0], A1[1], A1[2], A1[3]);
                uint32_t wAddr = wAddr0 + ks * 16 * LDK * 2;
#pragma unroll
                for (int g = 0; g < 4; g++) {
                    uint32_t b0, b1, b2, b3;
                    ldsm4t(wAddr + g * 32, b0, b1, b2, b3);
                    mma_bf16(acc[0][2 * g],     A0[0], A0[1], A0[2], A0[3], b0, b1);
                    mma_bf16(acc[0][2 * g + 1], A0[0], A0[1], A0[2], A0[3], b2, b3);
                    mma_bf16(acc[1][2 * g],     A1[0], A1[1], A1[2], A1[3], b0, b1);
                    mma_bf16(acc[1][2 * g + 1], A1[0], A1[1], A1[2], A1[3], b2, b3);
                }
            }
        }
        __syncthreads();
    }

    // spill accumulators to fp32 smem tile
    float* sC = (float*)smem;
    {
        int r0 = wr * 32 + (lane >> 2);
        int c0 = wc * 64 + (lane & 3) * 2;
#pragma unroll
        for (int mt = 0; mt < 2; mt++)
#pragma unroll
            for (int nt = 0; nt < 8; nt++) {
                int r = r0 + mt * 16;
                int c = c0 + nt * 8;
                sC[r * LDC + c]           = acc[mt][nt][0];
                sC[r * LDC + c + 1]       = acc[mt][nt][1];
                sC[(r + 8) * LDC + c]     = acc[mt][nt][2];
                sC[(r + 8) * LDC + c + 1] = acc[mt][nt][3];
            }
    }
    __syncthreads();

    float* sMean = (float*)(smem + OFF_MEAN);
    float* sRs   = (float*)(smem + OFF_RS);

    if (mode != 2) {
        int r = tid >> 1, h = tid & 1;
        int grow = rowBase + r;
        float s1 = 0.f, s2 = 0.f;
        const float4* b4 = (const float4*)bias;
        const float4* h4 = (const float4*)hin;
#pragma unroll
        for (int j = 0; j < 16; j++) {
            int c4 = h * 16 + j;
            float4 x = *(float4*)&sC[r * LDC + c4 * 4];
            float4 b = __ldg(&b4[c4]);
            x.x += b.x; x.y += b.y; x.z += b.z; x.w += b.w;
            if (mode == 1 && grow < NNODES) {
                float4 hv = __ldg(&h4[grow * 32 + c4]);
                x.x += hv.x; x.y += hv.y; x.z += hv.z; x.w += hv.w;
            }
            x.x = fmaxf(x.x, 0.f); x.y = fmaxf(x.y, 0.f);
            x.z = fmaxf(x.z, 0.f); x.w = fmaxf(x.w, 0.f);
            *(float4*)&sC[r * LDC + c4 * 4] = x;
            s1 += (x.x + x.y) + (x.z + x.w);
            s2 += (x.x * x.x + x.y * x.y) + (x.z * x.z + x.w * x.w);
        }
        s1 += __shfl_xor_sync(0xffffffffu, s1, 1);
        s2 += __shfl_xor_sync(0xffffffffu, s2, 1);
        if (h == 0) {
            float mean = s1 * (1.0f / 128.0f);
            float var  = s2 * (1.0f / 128.0f) - mean * mean;
            sMean[r] = mean;
            sRs[r]   = rsqrtf(var + 1e-5f);
        }
    }
    __syncthreads();

    {
        float4 gv  = __ldg(&((const float4*)gamma)[lane]);
        float4 btv = __ldg(&((const float4*)beta)[lane]);
        float4 bv  = __ldg(&((const float4*)bias)[lane]);
        float4* o4 = (float4*)hout;
#pragma unroll
        for (int p = 0; p < 16; p++) {
            int r = p * 8 + wid;
            int grow = rowBase + r;
            if (grow >= NNODES) continue;
            float4 x = *(float4*)&sC[r * LDC + lane * 4];
            if (mode != 2) {
                float mean = sMean[r], rs = sRs[r];
                x.x = (x.x - mean) * rs * gv.x + btv.x;
                x.y = (x.y - mean) * rs * gv.y + btv.y;
                x.z = (x.z - mean) * rs * gv.z + btv.z;
                x.w = (x.w - mean) * rs * gv.w + btv.w;
            } else {
                x.x += bv.x; x.y += bv.y; x.z += bv.z; x.w += bv.w;
            }
            o4[grow * 32 + lane] = x;
        }
    }
}

// ---------------- host ----------------
extern "C" void kernel_launch(void* const* d_in, const int* in_sizes, int n_in,
                              void* d_out, int out_size)
{
    const float* in_feat = (const float*)d_in[0];
    const int*   eidx    = (const int*)d_in[1];
    const float* W_rel   = (const float*)d_in[2];
    const float* b_rel   = (const float*)d_in[3];
    const float* W_root  = (const float*)d_in[4];
    const float* gamma   = (const float*)d_in[5];
    const float* beta    = (const float*)d_in[6];
    float* out = (float*)d_out;

    int E = in_sizes[1] / 2;
    const int* src = eidx;
    const int* dst = eidx + E;

    float *hA, *hB;
    cudaGetSymbolAddress((void**)&hA, g_hA);
    cudaGetSymbolAddress((void**)&hB, g_hB);

    cudaFuncSetAttribute(k_gemm_mma, cudaFuncAttributeMaxDynamicSharedMemorySize, GSM_TOTAL);

    int nb_nodes = (NNODES + 255) / 256;
    int nb_edges = (E + 255) / 256;
    int nb_scan  = (NNODES + 511) / 512;

    int spmm_blocks = (NNODES * 32 + 255) / 256;
    int gemm_blocks = (NNODES + 127) / 128;

    // CSR build — exactly 5 launches before the first k_spmm so ncu (-s 5 -c 1)
    // captures k_spmm. g_cnt is zeroed by the previous launch's k_scan1
    // (and statically for the very first).
    k_hist<<<nb_edges, 256>>>(dst, E);           // 0
    k_scan1<<<nb_scan, 512>>>();                 // 1 (also re-zeroes g_cnt)
    k_scan2<<<1, 256>>>(nb_scan);                // 2
    k_scan3<<<nb_nodes, 256>>>(E);               // 3
    k_scatter<<<nb_edges, 256>>>(src, dst, E);   // 4

    // layer 0
    k_spmm<<<spmm_blocks, 256>>>(in_feat);       // 5  <-- ncu capture target
    k_wsplit<<<8, 256>>>(W_rel, W_root);         // needed before first gemm only
    k_gemm_mma<<<gemm_blocks, 256, GSM_TOTAL>>>(in_feat, 0, b_rel, gamma, beta, hA, 0);
    // layer 1
    k_spmm<<<spmm_blocks, 256>>>(hA);
    k_gemm_mma<<<gemm_blocks, 256, GSM_TOTAL>>>(hA, 1, b_rel + 128, gamma, beta, hB, 1);
    // layer 2
    k_spmm<<<spmm_blocks, 256>>>(hB);
    k_gemm_mma<<<gemm_blocks, 256, GSM_TOTAL>>>(hB, 2, b_rel + 256, gamma, beta, hA, 1);
    // layer 3 (no epilogue)
    k_spmm<<<spmm_blocks, 256>>>(hA);
    k_gemm_mma<<<gemm_blocks, 256, GSM_TOTAL>>>(hA, 3, b_rel + 384, gamma, beta, out, 2);
}